// round 9
// baseline (speedup 1.0000x reference)
#include <cuda_runtime.h>
#include <cstdint>

// ----------------------------------------------------------------------------
// HandGNNEncoder: 2-layer GCN on a fixed 21-node skeleton + mean pool, fused.
//
//   h1 = relu( (A x) W1 + b1 )            (A x sparse: 44 nnz, 2 feature cols)
//   out = sum_s c[s] * h1[s,:] @ W2 + b2  where c[s] = (1/21) sum_t A[t,s]
//
// R9: occupancy-oriented rewrite. Phase-3 dot split across 2 d-halves so the
// register-resident W2 slice is 32 regs -> 4 CTAs/SM (32 warps). Next tile's
// x prefetched into registers during phase 1b (LDG latency off critical path).
// ----------------------------------------------------------------------------

#define R2 0.70710678118654752440f   // 1/sqrt(2)
#define R3 0.57735026918962576451f   // 1/sqrt(3)
#define T3 (1.0f/3.0f)
#define W23 (R2*R3)

static __device__ const int g_rowptr[22] = {
    0,1,3,5,7,9,11,13,15,17,20,22,24,26,29,31,33,35,38,40,42,44};
static __device__ const int g_cols[44] = {
    0,
    1,0,  2,1,  3,2,  4,3,
    5,0,  6,5,  7,6,  8,7,
    9,0,5,  10,9,  11,10,  12,11,
    13,0,9, 14,13, 15,14, 16,15,
    17,0,13,18,17, 19,18, 20,19};
static __device__ const float g_w[44] = {
    1.0f,
    0.5f,R2,  0.5f,0.5f,  0.5f,0.5f,  0.5f,0.5f,
    0.5f,R2,  0.5f,0.5f,  0.5f,0.5f,  0.5f,0.5f,
    T3,R3,W23, 0.5f,W23,  0.5f,0.5f,  0.5f,0.5f,
    T3,R3,T3,  0.5f,W23,  0.5f,0.5f,  0.5f,0.5f,
    T3,R3,T3,  0.5f,W23,  0.5f,0.5f,  0.5f,0.5f};

__constant__ float c_c[21] = {
    (1.0f + 2.0f*R2 + 3.0f*R3)/21.0f,
    1.0f/21.0f, 1.0f/21.0f, 1.0f/21.0f, 0.5f/21.0f,
    (1.0f + W23)/21.0f, 1.0f/21.0f, 1.0f/21.0f, 0.5f/21.0f,
    (2.0f/3.0f + W23)/21.0f, 1.0f/21.0f, 1.0f/21.0f, 0.5f/21.0f,
    (2.0f/3.0f + W23)/21.0f, 1.0f/21.0f, 1.0f/21.0f, 0.5f/21.0f,
    (1.0f/3.0f + W23)/21.0f, 1.0f/21.0f, 1.0f/21.0f, 0.5f/21.0f
};

#define NGRAPHS 32768
#define GPT     8               // graphs per tile
#define NTILES  (NGRAPHS/GPT)   // 4096
#define NBLOCKS 592             // 4 per SM (148 SMs), persistent
#define XA_STRIDE 44            // padded row (16B-aligned)
#define XPT     (GPT*42)        // 336 floats of x per tile

__device__ __forceinline__ void ffma2(unsigned long long& acc,
                                      unsigned long long a,
                                      unsigned long long b) {
    asm("fma.rn.f32x2 %0, %1, %2, %0;" : "+l"(acc) : "l"(a), "l"(b));
}
__device__ __forceinline__ unsigned long long packf2(float lo, float hi) {
    unsigned long long r;
    asm("mov.b64 %0, {%1,%2};" : "=l"(r) : "f"(lo), "f"(hi));
    return r;
}
__device__ __forceinline__ void unpackf2(unsigned long long v, float& lo, float& hi) {
    asm("mov.b64 {%0,%1}, %2;" : "=f"(lo), "=f"(hi) : "l"(v));
}

__global__ void __launch_bounds__(256, 4)
hand_gnn_kernel(const float* __restrict__ x,   // [G,21,2]
                const float* __restrict__ W1,  // [2,64]
                const float* __restrict__ b1,  // [64]
                const float* __restrict__ W2,  // [64,128]
                const float* __restrict__ b2,  // [128]
                float* __restrict__ out)       // [G,128]
{
    __shared__ float s_x[XPT];                // staged raw coords     (336)
    __shared__ float s_xa[GPT * XA_STRIDE];   // aggregated coords     (352)
    __shared__ float s_q[GPT * 64];           // pooled hidden         (512)
    __shared__ float s_part[2 * GPT * 128];   // phase-3 half-dots     (2048)

    const int t = threadIdx.x;

    // ---- phase-3 params: thread owns (feature f, d-half dh); 32-reg W2 slice
    const int f  = t & 127;
    const int dh = t >> 7;                    // 0/1: d in [32dh, 32dh+32)
    unsigned long long w2p[16];
#pragma unroll
    for (int i = 0; i < 16; ++i)
        w2p[i] = packf2(W2[(32*dh + 2*i    ) * 128 + f],
                        W2[(32*dh + 2*i + 1) * 128 + f]);
    const float b2f = b2[f];

    // ---- phase-2 params: thread owns hidden channel d2
    const int d2 = t & 63;
    const float w10 = W1[d2];
    const float w11 = W1[64 + d2];
    const float b1d = b1[d2];

    // ---- stage first tile's x ----
    int tile = blockIdx.x;
    {
        const float* xg = x + (size_t)tile * XPT;
        for (int i = t; i < XPT; i += 256) s_x[i] = xg[i];
    }
    __syncthreads();

    for (; tile < NTILES; tile += gridDim.x) {
        const int g0 = tile * GPT;

        // ---- prefetch next tile's x into registers (off critical path) ----
        int nt = tile + gridDim.x;
        const float* xn = x + (size_t)(nt < NTILES ? nt : tile) * XPT;
        const float px0 = xn[t];                          // t < 256 < 336
        const float px1 = (t < XPT - 256) ? xn[256 + t] : 0.0f;

        // ---- phase 1b: sparse aggregate xa[g][s][k] = sum_u A[s,u] x[g][u][k]
        for (int i = t; i < XPT; i += 256) {
            const int g = i / 42;
            const int j = i - g * 42;
            const int s = j >> 1;
            const int k = j & 1;
            float acc = 0.0f;
            const int e0 = g_rowptr[s], e1 = g_rowptr[s + 1];
            for (int e = e0; e < e1; ++e)
                acc = fmaf(g_w[e], s_x[g * 42 + (g_cols[e] << 1) + k], acc);
            s_xa[g * XA_STRIDE + j] = acc;
        }
        __syncthreads();                                  // xa ready; s_x free

        // ---- drop prefetched x into shared (visible after next barrier) ----
        s_x[t] = px0;
        if (t < XPT - 256) s_x[256 + t] = px1;

        // ---- phase 2: q[g][d] = sum_s c[s]*relu(xa.W1 + b1) ----
#pragma unroll
        for (int j = 0; j < 2; ++j) {
            const int g = (t >> 6) + 4 * j;               // warp-uniform
            const float4* xa4 = (const float4*)&s_xa[g * XA_STRIDE];
            float acc = 0.0f;
#pragma unroll
            for (int i = 0; i < 10; ++i) {                // s = 2i, 2i+1
                const float4 a = xa4[i];                  // broadcast LDS.128
                float v0 = fmaf(a.x, w10, fmaf(a.y, w11, b1d));
                v0 = fmaxf(v0, 0.0f);
                acc = fmaf(v0, c_c[2*i], acc);
                float v1 = fmaf(a.z, w10, fmaf(a.w, w11, b1d));
                v1 = fmaxf(v1, 0.0f);
                acc = fmaf(v1, c_c[2*i+1], acc);
            }
            const float2 al = *(const float2*)&s_xa[g * XA_STRIDE + 40];
            float v = fmaf(al.x, w10, fmaf(al.y, w11, b1d));
            v = fmaxf(v, 0.0f);
            acc = fmaf(v, c_c[20], acc);
            s_q[g * 64 + d2] = acc;
        }
        __syncthreads();                                  // q ready

        // ---- phase 3: half-column dots (packed FFMA2), partials to shared ---
#pragma unroll
        for (int g = 0; g < GPT; ++g) {
            const ulonglong2* qv = (const ulonglong2*)&s_q[g * 64 + 32 * dh];
            unsigned long long a0 = 0ull, a1 = 0ull;
#pragma unroll
            for (int i = 0; i < 8; ++i) {
                const ulonglong2 q2 = qv[i];              // broadcast LDS.128
                ffma2(a0, q2.x, w2p[2*i]);
                ffma2(a1, q2.y, w2p[2*i+1]);
            }
            float l0, h0, l1, h1;
            unpackf2(a0, l0, h0);
            unpackf2(a1, l1, h1);
            s_part[dh * (GPT*128) + g * 128 + f] = (l0 + h0) + (l1 + h1);
        }
        __syncthreads();                                  // partials ready

        // ---- reduce halves + bias, coalesced store ----
#pragma unroll
        for (int j = 0; j < 4; ++j) {
            const int g = (t >> 7) + 2 * j;               // warp-uniform
            const float v = s_part[g * 128 + f]
                          + s_part[GPT*128 + g * 128 + f] + b2f;
            out[(size_t)(g0 + g) * 128 + f] = v;
        }
        __syncthreads();   // s_q/s_part free; s_x(t+1) visible for next 1b
    }
}

extern "C" void kernel_launch(void* const* d_in, const int* in_sizes, int n_in,
                              void* d_out, int out_size)
{
    const float* x  = (const float*)d_in[0];  // hand_landmarks [64,512,21,2]
    const float* W1 = (const float*)d_in[1];  // [2,64]
    const float* b1 = (const float*)d_in[2];  // [64]
    const float* W2 = (const float*)d_in[3];  // [64,128]
    const float* b2 = (const float*)d_in[4];  // [128]
    float* out = (float*)d_out;               // [64,512,128]

    hand_gnn_kernel<<<NBLOCKS, 256>>>(x, W1, b1, W2, b2, out);
}

// round 10
// speedup vs baseline: 1.0202x; 1.0202x over previous
#include <cuda_runtime.h>
#include <cstdint>

// ----------------------------------------------------------------------------
// HandGNNEncoder: 2-layer GCN on a fixed 21-node skeleton + mean pool, fused.
//
//   h1 = relu( (A x) W1 + b1 )            (A x sparse: 44 nnz, 2 feature cols)
//   out = sum_s c[s] * h1[s,:] @ W2 + b2  where c[s] = (1/21) sum_t A[t,s]
//
// R10: instruction-count rewrite. Phase 2 runs packed f32x2 over GRAPH PAIRS
// (aggregated coords stored transposed [k][s][g], graphs contiguous), phase 3
// keeps the half-d FFMA2 matvec (32-reg W2 slice, 4 CTAs/SM).
// ----------------------------------------------------------------------------

#define R2 0.70710678118654752440f   // 1/sqrt(2)
#define R3 0.57735026918962576451f   // 1/sqrt(3)
#define T3 (1.0f/3.0f)
#define W23 (R2*R3)

static __device__ const int g_rowptr[22] = {
    0,1,3,5,7,9,11,13,15,17,20,22,24,26,29,31,33,35,38,40,42,44};
static __device__ const int g_cols[44] = {
    0,
    1,0,  2,1,  3,2,  4,3,
    5,0,  6,5,  7,6,  8,7,
    9,0,5,  10,9,  11,10,  12,11,
    13,0,9, 14,13, 15,14, 16,15,
    17,0,13,18,17, 19,18, 20,19};
static __device__ const float g_w[44] = {
    1.0f,
    0.5f,R2,  0.5f,0.5f,  0.5f,0.5f,  0.5f,0.5f,
    0.5f,R2,  0.5f,0.5f,  0.5f,0.5f,  0.5f,0.5f,
    T3,R3,W23, 0.5f,W23,  0.5f,0.5f,  0.5f,0.5f,
    T3,R3,T3,  0.5f,W23,  0.5f,0.5f,  0.5f,0.5f,
    T3,R3,T3,  0.5f,W23,  0.5f,0.5f,  0.5f,0.5f};

// c_c duplicated into both halves of a float2 for packed FFMA2.
#define CC(v) {(v),(v)}
static __constant__ float2 c_c2[21] = {
    CC((1.0f + 2.0f*R2 + 3.0f*R3)/21.0f),
    CC(1.0f/21.0f), CC(1.0f/21.0f), CC(1.0f/21.0f), CC(0.5f/21.0f),
    CC((1.0f + W23)/21.0f), CC(1.0f/21.0f), CC(1.0f/21.0f), CC(0.5f/21.0f),
    CC((2.0f/3.0f + W23)/21.0f), CC(1.0f/21.0f), CC(1.0f/21.0f), CC(0.5f/21.0f),
    CC((2.0f/3.0f + W23)/21.0f), CC(1.0f/21.0f), CC(1.0f/21.0f), CC(0.5f/21.0f),
    CC((1.0f/3.0f + W23)/21.0f), CC(1.0f/21.0f), CC(1.0f/21.0f), CC(0.5f/21.0f)
};

#define NGRAPHS 32768
#define GPT     8               // graphs per tile
#define NTILES  (NGRAPHS/GPT)   // 4096
#define NBLOCKS 592             // 4 per SM (148 SMs), persistent, ~1% tail
#define XPT     (GPT*42)        // 336 floats of x per tile

typedef unsigned long long u64;

__device__ __forceinline__ void ffma2(u64& acc, u64 a, u64 b) {
    asm("fma.rn.f32x2 %0, %1, %2, %0;" : "+l"(acc) : "l"(a), "l"(b));
}
__device__ __forceinline__ u64 fma2(u64 a, u64 b, u64 c) {
    u64 d;
    asm("fma.rn.f32x2 %0, %1, %2, %3;" : "=l"(d) : "l"(a), "l"(b), "l"(c));
    return d;
}
__device__ __forceinline__ u64 packf2(float lo, float hi) {
    u64 r;
    asm("mov.b64 %0, {%1,%2};" : "=l"(r) : "f"(lo), "f"(hi));
    return r;
}
__device__ __forceinline__ void unpackf2(u64 v, float& lo, float& hi) {
    asm("mov.b64 {%0,%1}, %2;" : "=f"(lo), "=f"(hi) : "l"(v));
}

__global__ void __launch_bounds__(256, 4)
hand_gnn_kernel(const float* __restrict__ x,   // [G,21,2]
                const float* __restrict__ W1,  // [2,64]
                const float* __restrict__ b1,  // [64]
                const float* __restrict__ W2,  // [64,128]
                const float* __restrict__ b2,  // [128]
                float* __restrict__ out)       // [G,128]
{
    __shared__ float s_x[XPT];                // staged raw coords        (336)
    __shared__ float s_xa[2 * 21 * GPT];      // transposed agg [k][s][g] (336)
    __shared__ float s_q[GPT * 64];           // pooled hidden            (512)
    __shared__ float s_part[2 * GPT * 128];   // phase-3 half-dots        (2048)

    const int t = threadIdx.x;

    // ---- phase-3 params: (feature f, d-half dh); 32-reg packed W2 slice ----
    const int f  = t & 127;
    const int dh = t >> 7;                    // d in [32dh, 32dh+32)
    u64 w2p[16];
#pragma unroll
    for (int i = 0; i < 16; ++i)
        w2p[i] = packf2(W2[(32*dh + 2*i    ) * 128 + f],
                        W2[(32*dh + 2*i + 1) * 128 + f]);
    const float b2f = b2[f];

    // ---- phase-2 params: (hidden channel d2, graph-pair gp); packed W1 ----
    const int d2 = t & 63;
    const int gp = t >> 6;                    // graphs (2gp, 2gp+1)
    const u64 w10p = packf2(W1[d2],      W1[d2]);
    const u64 w11p = packf2(W1[64 + d2], W1[64 + d2]);
    const u64 b1p  = packf2(b1[d2],      b1[d2]);

    // ---- stage first tile's x ----
    int tile = blockIdx.x;
    {
        const float* xg = x + (size_t)tile * XPT;
        for (int i = t; i < XPT; i += 256) s_x[i] = xg[i];
    }
    __syncthreads();

    for (; tile < NTILES; tile += gridDim.x) {
        const int g0 = tile * GPT;

        // ---- prefetch next tile's x into registers ----
        int nt = tile + gridDim.x;
        const float* xn = x + (size_t)(nt < NTILES ? nt : tile) * XPT;
        const float px0 = xn[t];                           // t < 256 < 336
        const float px1 = (t < XPT - 256) ? xn[256 + t] : 0.0f;

        // ---- phase 1b: sparse aggregate, TRANSPOSED store [k][s][g] ----
        for (int i = t; i < XPT; i += 256) {
            const int g = i & 7;
            const int j = i >> 3;             // 0..41
            const int s = j >> 1;
            const int k = j & 1;
            float acc = 0.0f;
            const int e0 = g_rowptr[s], e1 = g_rowptr[s + 1];
            for (int e = e0; e < e1; ++e)
                acc = fmaf(g_w[e], s_x[g * 42 + (g_cols[e] << 1) + k], acc);
            s_xa[k * (21 * GPT) + s * GPT + g] = acc;
        }
        __syncthreads();                                   // xa ready; s_x free

        // ---- drop prefetched x into shared ----
        s_x[t] = px0;
        if (t < XPT - 256) s_x[256 + t] = px1;

        // ---- phase 2 (packed over graph pair): q[g][d2] ----
        {
            u64 acc = 0ull;
            const int gb = 2 * gp;                         // warp-uniform
#pragma unroll
            for (int s = 0; s < 21; ++s) {
                const u64 xx = *(const u64*)&s_xa[             s * GPT + gb];
                const u64 yy = *(const u64*)&s_xa[21 * GPT +   s * GPT + gb];
                u64 v = fma2(xx, w10p, fma2(yy, w11p, b1p));
                float vl, vh;
                unpackf2(v, vl, vh);
                vl = fmaxf(vl, 0.0f);
                vh = fmaxf(vh, 0.0f);
                const u64 vp = packf2(vl, vh);
                const u64 cc = *(const u64*)&c_c2[s];       // LDC.64 (uniform)
                ffma2(acc, vp, cc);
            }
            float q0, q1;
            unpackf2(acc, q0, q1);
            s_q[(gb    ) * 64 + d2] = q0;
            s_q[(gb + 1) * 64 + d2] = q1;
        }
        __syncthreads();                                   // q ready

        // ---- phase 3: half-column dots (packed FFMA2) ----
#pragma unroll
        for (int g = 0; g < GPT; ++g) {
            const ulonglong2* qv = (const ulonglong2*)&s_q[g * 64 + 32 * dh];
            u64 a0 = 0ull, a1 = 0ull;
#pragma unroll
            for (int i = 0; i < 8; ++i) {
                const ulonglong2 q2 = qv[i];               // broadcast LDS.128
                ffma2(a0, q2.x, w2p[2*i]);
                ffma2(a1, q2.y, w2p[2*i+1]);
            }
            float l0, h0, l1, h1;
            unpackf2(a0, l0, h0);
            unpackf2(a1, l1, h1);
            s_part[dh * (GPT*128) + g * 128 + f] = (l0 + h0) + (l1 + h1);
        }
        __syncthreads();                                   // partials ready

        // ---- reduce halves + bias, coalesced store ----
#pragma unroll
        for (int j = 0; j < 4; ++j) {
            const int g = (t >> 7) + 2 * j;                // warp-uniform
            const float v = s_part[g * 128 + f]
                          + s_part[GPT*128 + g * 128 + f] + b2f;
            out[(size_t)(g0 + g) * 128 + f] = v;
        }
        __syncthreads();   // s_q/s_part free; s_x(t+1) visible for next 1b
    }
}

extern "C" void kernel_launch(void* const* d_in, const int* in_sizes, int n_in,
                              void* d_out, int out_size)
{
    const float* x  = (const float*)d_in[0];  // hand_landmarks [64,512,21,2]
    const float* W1 = (const float*)d_in[1];  // [2,64]
    const float* b1 = (const float*)d_in[2];  // [64]
    const float* W2 = (const float*)d_in[3];  // [64,128]
    const float* b2 = (const float*)d_in[4];  // [128]
    float* out = (float*)d_out;               // [64,512,128]

    hand_gnn_kernel<<<NBLOCKS, 256>>>(x, W1, b1, W2, b2, out);
}

// round 13
// speedup vs baseline: 1.6757x; 1.6425x over previous
#include <cuda_runtime.h>
#include <cuda_bf16.h>
#include <cstdint>

typedef unsigned long long u64;
typedef unsigned int       u32;
typedef unsigned short     u16;

// ---------------------------------------------------------------------------
// HandGNNEncoder (2-layer GCN on fixed 21-node skeleton + mean pool), fused:
//   xa = A_norm x                 (sparse 44-nnz, unrolled per-thread)
//   q[g,d] = sum_s c[s]*relu(xa[g,s,:].W1[:,d] + b1[d])     (fp32, f32x2)
//   out    = q @ W2 + b2          (mma.sync bf16 split-precision, 3 passes)
// NOTE: harness compiles via compute_103 (non-'a') -> tcgen05 unavailable,
// but classic mma.sync/ldmatrix (sm_80 baseline) are fine.
// ---------------------------------------------------------------------------

#define R2f  0.70710678118654752440f
#define R3f  0.57735026918962576451f
#define T3f  (1.0f/3.0f)
#define W23f (R2f*R3f)

__constant__ float CCv[21] = {
    (1.0f + 2.0f*R2f + 3.0f*R3f)/21.0f,
    1.0f/21.0f, 1.0f/21.0f, 1.0f/21.0f, 0.5f/21.0f,
    (1.0f + W23f)/21.0f, 1.0f/21.0f, 1.0f/21.0f, 0.5f/21.0f,
    (2.0f/3.0f + W23f)/21.0f, 1.0f/21.0f, 1.0f/21.0f, 0.5f/21.0f,
    (2.0f/3.0f + W23f)/21.0f, 1.0f/21.0f, 1.0f/21.0f, 0.5f/21.0f,
    (1.0f/3.0f + W23f)/21.0f, 1.0f/21.0f, 1.0f/21.0f, 0.5f/21.0f
};

#define NGRAPHS 32768
#define TILE_G  128
#define NCTAS   (NGRAPHS/TILE_G)   // 256

// smem layout (bytes). A/B tiles have 144B row pitch (72 bf16): 16B-aligned,
// odd multiple of 16B -> conflict-free ldmatrix.
#define SM_B2  0                   // 128 floats
#define SM_XA  1024                // 2 planes * 21 * 128 floats = 21504
#define SM_AH  22528               // q hi  [128 m][72] bf16 = 18432
#define SM_AL  40960               // q lo
#define SM_BH  59392               // W2^T hi [128 n][72] bf16
#define SM_BL  77824               // W2^T lo
#define SM_TOT 96256

__device__ __forceinline__ u32 smem_u32(const void* p) {
    u32 a;
    asm("{ .reg .u64 t; cvta.to.shared.u64 t, %1; cvt.u32.u64 %0, t; }"
        : "=r"(a) : "l"(p));
    return a;
}
__device__ __forceinline__ u64 packf2(float lo, float hi) {
    u64 r; asm("mov.b64 %0, {%1,%2};" : "=l"(r) : "f"(lo), "f"(hi)); return r;
}
__device__ __forceinline__ void unpackf2(u64 v, float& lo, float& hi) {
    asm("mov.b64 {%0,%1}, %2;" : "=f"(lo), "=f"(hi) : "l"(v));
}
__device__ __forceinline__ u64 fma2(u64 a, u64 b, u64 c) {
    u64 d; asm("fma.rn.f32x2 %0, %1, %2, %3;" : "=l"(d) : "l"(a), "l"(b), "l"(c));
    return d;
}
// result: lo half = bf16(a), hi half = bf16(b)
__device__ __forceinline__ u32 cvt_bf16x2(float a, float b) {
    u32 r; asm("cvt.rn.bf16x2.f32 %0, %1, %2;" : "=r"(r) : "f"(b), "f"(a));
    return r;
}
__device__ __forceinline__ void ldsm_x4(u32& r0, u32& r1, u32& r2, u32& r3, u32 a) {
    asm volatile("ldmatrix.sync.aligned.m8n8.x4.shared.b16 {%0,%1,%2,%3}, [%4];"
                 : "=r"(r0), "=r"(r1), "=r"(r2), "=r"(r3) : "r"(a));
}
__device__ __forceinline__ void ldsm_x2(u32& r0, u32& r1, u32 a) {
    asm volatile("ldmatrix.sync.aligned.m8n8.x2.shared.b16 {%0,%1}, [%2];"
                 : "=r"(r0), "=r"(r1) : "r"(a));
}
__device__ __forceinline__ void mma_bf16(float* c, const u32* a, const u32* b) {
    asm volatile("mma.sync.aligned.m16n8k16.row.col.f32.bf16.bf16.f32 "
                 "{%0,%1,%2,%3},{%4,%5,%6,%7},{%8,%9},{%0,%1,%2,%3};"
                 : "+f"(c[0]), "+f"(c[1]), "+f"(c[2]), "+f"(c[3])
                 : "r"(a[0]), "r"(a[1]), "r"(a[2]), "r"(a[3]),
                   "r"(b[0]), "r"(b[1]));
}

__global__ void __launch_bounds__(256, 2)
hand_gnn_mma_kernel(const float* __restrict__ x,   // [G,21,2]
                    const float* __restrict__ W1,  // [2,64]
                    const float* __restrict__ b1,  // [64]
                    const float* __restrict__ W2,  // [64,128]
                    const float* __restrict__ b2,  // [128]
                    float* __restrict__ out)       // [G,128]
{
    extern __shared__ char smem[];
    float* b2s = (float*)(smem + SM_B2);
    float* xa  = (float*)(smem + SM_XA);   // plane0: x-coord, plane1 at +2688
    const int t  = threadIdx.x;
    const int g0 = blockIdx.x * TILE_G;

    // ---- build B tiles: W2^T split bf16 hi/lo, [f-row][d-col], pitch 72 ----
    {
        u16* bh = (u16*)(smem + SM_BH);
        u16* bl = (u16*)(smem + SM_BL);
        for (int i = t; i < 64 * 128; i += 256) {
            const float w = W2[i];             // i = d*128 + f (coalesced)
            const int dd = i >> 7, ff = i & 127;
            __nv_bfloat16 hb = __float2bfloat16(w);
            const float hf = __bfloat162float(hb);
            __nv_bfloat16 lb = __float2bfloat16(w - hf);
            bh[ff * 72 + dd] = reinterpret_cast<u16&>(hb);
            bl[ff * 72 + dd] = reinterpret_cast<u16&>(lb);
        }
        if (t < 128) b2s[t] = b2[t];
    }

    // ---- phase 1: per-thread sparse aggregation (graph = thread) ----
    if (t < 128) {
        const float2* xp = (const float2*)x + (size_t)(g0 + t) * 21;
        float2 v[21];
#pragma unroll
        for (int s = 0; s < 21; ++s) v[s] = __ldg(&xp[s]);
        float2 a[21];
        a[0].x = v[0].x;                     a[0].y = v[0].y;
        a[1].x = 0.5f*v[1].x + R2f*v[0].x;   a[1].y = 0.5f*v[1].y + R2f*v[0].y;
        a[2].x = 0.5f*(v[2].x + v[1].x);     a[2].y = 0.5f*(v[2].y + v[1].y);
        a[3].x = 0.5f*(v[3].x + v[2].x);     a[3].y = 0.5f*(v[3].y + v[2].y);
        a[4].x = 0.5f*(v[4].x + v[3].x);     a[4].y = 0.5f*(v[4].y + v[3].y);
        a[5].x = 0.5f*v[5].x + R2f*v[0].x;   a[5].y = 0.5f*v[5].y + R2f*v[0].y;
        a[6].x = 0.5f*(v[6].x + v[5].x);     a[6].y = 0.5f*(v[6].y + v[5].y);
        a[7].x = 0.5f*(v[7].x + v[6].x);     a[7].y = 0.5f*(v[7].y + v[6].y);
        a[8].x = 0.5f*(v[8].x + v[7].x);     a[8].y = 0.5f*(v[8].y + v[7].y);
        a[9].x  = T3f*v[9].x + R3f*v[0].x + W23f*v[5].x;
        a[9].y  = T3f*v[9].y + R3f*v[0].y + W23f*v[5].y;
        a[10].x = 0.5f*v[10].x + W23f*v[9].x; a[10].y = 0.5f*v[10].y + W23f*v[9].y;
        a[11].x = 0.5f*(v[11].x + v[10].x);  a[11].y = 0.5f*(v[11].y + v[10].y);
        a[12].x = 0.5f*(v[12].x + v[11].x);  a[12].y = 0.5f*(v[12].y + v[11].y);
        a[13].x = T3f*v[13].x + R3f*v[0].x + T3f*v[9].x;
        a[13].y = T3f*v[13].y + R3f*v[0].y + T3f*v[9].y;
        a[14].x = 0.5f*v[14].x + W23f*v[13].x; a[14].y = 0.5f*v[14].y + W23f*v[13].y;
        a[15].x = 0.5f*(v[15].x + v[14].x);  a[15].y = 0.5f*(v[15].y + v[14].y);
        a[16].x = 0.5f*(v[16].x + v[15].x);  a[16].y = 0.5f*(v[16].y + v[15].y);
        a[17].x = T3f*v[17].x + R3f*v[0].x + T3f*v[13].x;
        a[17].y = T3f*v[17].y + R3f*v[0].y + T3f*v[13].y;
        a[18].x = 0.5f*v[18].x + W23f*v[17].x; a[18].y = 0.5f*v[18].y + W23f*v[17].y;
        a[19].x = 0.5f*(v[19].x + v[18].x);  a[19].y = 0.5f*(v[19].y + v[18].y);
        a[20].x = 0.5f*(v[20].x + v[19].x);  a[20].y = 0.5f*(v[20].y + v[19].y);
#pragma unroll
        for (int s = 0; s < 21; ++s) {       // transposed planes [k][s][g]
            xa[s * 128 + t]        = a[s].x;
            xa[2688 + s * 128 + t] = a[s].y;
        }
    }
    __syncthreads();                          // xa + B tiles ready

    // ---- phase 2: q over graph pairs (f32x2), split-bf16 into A tiles ----
    {
        const int d  = t & 63;                // hidden channel (scalar)
        const int gq = t >> 6;                // 32-graph block
        const u64 w0p = packf2(W1[d], W1[d]);
        const u64 w1p = packf2(W1[64 + d], W1[64 + d]);
        const u64 b1p = packf2(b1[d], b1[d]);
        u64 acc2[16];
#pragma unroll
        for (int j = 0; j < 16; ++j) acc2[j] = 0ull;

#pragma unroll
        for (int s = 0; s < 21; ++s) {
            const u64 ccp = packf2(CCv[s], CCv[s]);
            const int bo = s * 128 + 32 * gq;
#pragma unroll
            for (int h = 0; h < 2; ++h) {     // halves of 16 graphs
                const ulonglong2 xA = *(const ulonglong2*)&xa[bo + 16*h];
                const ulonglong2 xB = *(const ulonglong2*)&xa[bo + 16*h + 4];
                const ulonglong2 xC = *(const ulonglong2*)&xa[bo + 16*h + 8];
                const ulonglong2 xD = *(const ulonglong2*)&xa[bo + 16*h + 12];
                const ulonglong2 yA = *(const ulonglong2*)&xa[2688 + bo + 16*h];
                const ulonglong2 yB = *(const ulonglong2*)&xa[2688 + bo + 16*h + 4];
                const ulonglong2 yC = *(const ulonglong2*)&xa[2688 + bo + 16*h + 8];
                const ulonglong2 yD = *(const ulonglong2*)&xa[2688 + bo + 16*h + 12];
#define PROC(xx, yy, idx) do {                                      \
    u64 _v = fma2((xx), w0p, fma2((yy), w1p, b1p));                 \
    float _a, _b; unpackf2(_v, _a, _b);                             \
    _a = fmaxf(_a, 0.0f); _b = fmaxf(_b, 0.0f);                     \
    acc2[idx] = fma2(packf2(_a, _b), ccp, acc2[idx]); } while (0)
                PROC(xA.x, yA.x, 8*h + 0);  PROC(xA.y, yA.y, 8*h + 1);
                PROC(xB.x, yB.x, 8*h + 2);  PROC(xB.y, yB.y, 8*h + 3);
                PROC(xC.x, yC.x, 8*h + 4);  PROC(xC.y, yC.y, 8*h + 5);
                PROC(xD.x, yD.x, 8*h + 6);  PROC(xD.y, yD.y, 8*h + 7);
#undef PROC
            }
        }
        // split-bf16 store into A tiles (row = graph, col = d, pitch 72 u16)
        u16* ah = (u16*)(smem + SM_AH);
        u16* al = (u16*)(smem + SM_AL);
#pragma unroll
        for (int j = 0; j < 16; ++j) {
            float q0, q1; unpackf2(acc2[j], q0, q1);
            const u32 hh = cvt_bf16x2(q0, q1);          // lo=bf(q0) hi=bf(q1)
            const float f0 = __uint_as_float(hh << 16);
            const float f1 = __uint_as_float(hh & 0xffff0000u);
            const u32 ll = cvt_bf16x2(q0 - f0, q1 - f1);
            const int g = 32 * gq + 2 * j;
            const int o = g * 72 + d;
            ah[o] = (u16)hh;  ah[o + 72] = (u16)(hh >> 16);
            al[o] = (u16)ll;  al[o + 72] = (u16)(ll >> 16);
        }
    }
    __syncthreads();                          // A tiles ready

    // ---- phase 3: 128x128x64 GEMM, 3 split passes of m16n8k16 bf16 ----
    {
        const int wid  = t >> 5;
        const int lane = t & 31;
        const int m0 = (wid & 1) * 64;        // 64 graph rows per warp
        const int n0 = (wid >> 1) * 32;       // 32 feature cols per warp

        const u32 sbase = smem_u32(smem);
        const u32 aRow = (lane & 15), aSel = (lane >> 4) << 4;
        const u32 bRow = (lane & 7),  bSel = ((lane >> 3) & 1) << 4;
        const u32 aH = sbase + SM_AH + (m0 + aRow) * 144 + aSel;
        const u32 aL = sbase + SM_AL + (m0 + aRow) * 144 + aSel;
        const u32 bH = sbase + SM_BH + (n0 + bRow) * 144 + bSel;
        const u32 bL = sbase + SM_BL + (n0 + bRow) * 144 + bSel;

        float acc[4][4][4];
#pragma unroll
        for (int mt = 0; mt < 4; ++mt)
#pragma unroll
            for (int nt = 0; nt < 4; ++nt)
#pragma unroll
                for (int r = 0; r < 4; ++r) acc[mt][nt][r] = 0.0f;

        // pass 1+2: Ah * (Bh + Bl)
#pragma unroll
        for (int kt = 0; kt < 4; ++kt) {
            u32 af[4][4];
#pragma unroll
            for (int mt = 0; mt < 4; ++mt)
                ldsm_x4(af[mt][0], af[mt][1], af[mt][2], af[mt][3],
                        aH + mt * (16 * 144) + kt * 32);
            u32 bf[4][2];
#pragma unroll
            for (int nt = 0; nt < 4; ++nt)
                ldsm_x2(bf[nt][0], bf[nt][1], bH + nt * (8 * 144) + kt * 32);
#pragma unroll
            for (int mt = 0; mt < 4; ++mt)
#pragma unroll
                for (int nt = 0; nt < 4; ++nt)
                    mma_bf16(acc[mt][nt], af[mt], bf[nt]);
#pragma unroll
            for (int nt = 0; nt < 4; ++nt)
                ldsm_x2(bf[nt][0], bf[nt][1], bL + nt * (8 * 144) + kt * 32);
#pragma unroll
            for (int mt = 0; mt < 4; ++mt)
#pragma unroll
                for (int nt = 0; nt < 4; ++nt)
                    mma_bf16(acc[mt][nt], af[mt], bf[nt]);
        }
        // pass 3: Al * Bh
#pragma unroll
        for (int kt = 0; kt < 4; ++kt) {
            u32 af[4][4];
#pragma unroll
            for (int mt = 0; mt < 4; ++mt)
                ldsm_x4(af[mt][0], af[mt][1], af[mt][2], af[mt][3],
                        aL + mt * (16 * 144) + kt * 32);
            u32 bf[4][2];
#pragma unroll
            for (int nt = 0; nt < 4; ++nt)
                ldsm_x2(bf[nt][0], bf[nt][1], bH + nt * (8 * 144) + kt * 32);
#pragma unroll
            for (int mt = 0; mt < 4; ++mt)
#pragma unroll
                for (int nt = 0; nt < 4; ++nt)
                    mma_bf16(acc[mt][nt], af[mt], bf[nt]);
        }

        // ---- epilogue: bias + store (fragment layout m16n8) ----
        const int r0 = m0 + (lane >> 2);
        const int c0 = n0 + 2 * (lane & 3);
#pragma unroll
        for (int mt = 0; mt < 4; ++mt) {
#pragma unroll
            for (int nt = 0; nt < 4; ++nt) {
                const int row = g0 + r0 + 16 * mt;
                const int col = c0 + 8 * nt;
                const float2 bb = *(const float2*)&b2s[col];
                float2 v0, v1;
                v0.x = acc[mt][nt][0] + bb.x;  v0.y = acc[mt][nt][1] + bb.y;
                v1.x = acc[mt][nt][2] + bb.x;  v1.y = acc[mt][nt][3] + bb.y;
                *(float2*)&out[(size_t)row * 128 + col] = v0;
                *(float2*)&out[(size_t)(row + 8) * 128 + col] = v1;
            }
        }
    }
}

extern "C" void kernel_launch(void* const* d_in, const int* in_sizes, int n_in,
                              void* d_out, int out_size)
{
    const float* x  = (const float*)d_in[0];  // hand_landmarks [64,512,21,2]
    const float* W1 = (const float*)d_in[1];  // [2,64]
    const float* b1 = (const float*)d_in[2];  // [64]
    const float* W2 = (const float*)d_in[3];  // [64,128]
    const float* b2 = (const float*)d_in[4];  // [128]
    float* out = (float*)d_out;               // [64,512,128]

    cudaFuncSetAttribute(hand_gnn_mma_kernel,
                         cudaFuncAttributeMaxDynamicSharedMemorySize, SM_TOT);
    hand_gnn_mma_kernel<<<NCTAS, 256, SM_TOT>>>(x, W1, b1, W2, b2, out);
}